// round 7
// baseline (speedup 1.0000x reference)
#include <cuda_runtime.h>
#include <math.h>

#define BB 8
#define CC 256
#define HH 56
#define WW 56
#define HW (HH*WW)          // 3136
#define KK 3
#define TAPS 9
#define MID 51
#define CKK (CC*TAPS)       // 2304
#define GAIN_OVER_K 0.4714045207910317f   // sqrt(2)/3

__device__ float g_pooled[BB * CC];
__device__ float g_sf[BB * TAPS * HW];
__device__ float g_cf[BB * CKK];

typedef unsigned long long ull;

// ---- f32x2 packed helpers (sm_103a) --------------------------------------
__device__ __forceinline__ ull pack2(float x, float y) {
    ull r; asm("mov.b64 %0, {%1, %2};" : "=l"(r) : "f"(x), "f"(y)); return r;
}
__device__ __forceinline__ void unpack2(ull v, float& x, float& y) {
    asm("mov.b64 {%0, %1}, %2;" : "=f"(x), "=f"(y) : "l"(v));
}
__device__ __forceinline__ ull mul2(ull a, ull b) {
    ull d; asm("mul.rn.f32x2 %0, %1, %2;" : "=l"(d) : "l"(a), "l"(b)); return d;
}
__device__ __forceinline__ ull add2(ull a, ull b) {
    ull d; asm("add.rn.f32x2 %0, %1, %2;" : "=l"(d) : "l"(a), "l"(b)); return d;
}
__device__ __forceinline__ ull fma2(ull a, ull b, ull c) {
    ull d; asm("fma.rn.f32x2 %0, %1, %2, %3;" : "=l"(d) : "l"(a), "l"(b), "l"(c)); return d;
}

// ---------------------------------------------------------------------------
// Kernel A: block-specialized. bx < 49 -> sf (64-px tile, 2 px/thread, f32x2)
//                              bx >= 49 -> pooled means (warp per channel)
// ---------------------------------------------------------------------------
__global__ void __launch_bounds__(512) kA_sf_pool(
    const float* __restrict__ x,
    const float* __restrict__ ws,
    const float* __restrict__ bs)
{
    __shared__ ull ws_s2[CC * 10];            // dup'd (w,w) pairs, 20 KB
    __shared__ ull red2[16 * TAPS * 32];      // 36 KB

    const int b    = blockIdx.y;
    const int bx   = blockIdx.x;
    const int tid  = threadIdx.x;
    const int lane = tid & 31;
    const int w    = tid >> 5;

    if (bx >= 49) {
        const int c = (bx - 49) * 16 + w;
        const float4* p4 = (const float4*)(x + ((size_t)b * CC + c) * HW);
        float s = 0.f;
        for (int j = lane; j < 784; j += 32) {
            float4 v = __ldg(p4 + j);
            s += (v.x + v.y) + (v.z + v.w);
        }
#pragma unroll
        for (int o = 16; o > 0; o >>= 1) s += __shfl_xor_sync(0xffffffffu, s, o);
        if (lane == 0) g_pooled[b * CC + c] = s * (1.f / (float)HW);
        return;
    }

    // stage ws duplicated: ws[n*256+c] -> ws_s2[c*10+n] = (w,w)
    for (int i = tid; i < TAPS * CC; i += 512) {
        int n = i >> 8, c = i & 255;
        float v = ws[i];
        ws_s2[c * 10 + n] = pack2(v, v);
    }
    __syncthreads();

    // warp w owns channels [w*16, w*16+16); lane owns pixel pair 2*lane
    const int pix = bx * 64 + 2 * lane;
    const float* xb = x + ((size_t)b * CC + w * 16) * HW + pix;

    ull acc2[TAPS];
#pragma unroll
    for (int n = 0; n < TAPS; n++) acc2[n] = 0ULL;

#pragma unroll
    for (int cc = 0; cc < 16; cc++) {
        ull xv2 = __ldg((const ull*)(xb + (size_t)cc * HW));   // 2 px packed
        const ull* wr = ws_s2 + (w * 16 + cc) * 10;
#pragma unroll
        for (int n = 0; n < TAPS; n++)
            acc2[n] = fma2(xv2, wr[n], acc2[n]);
    }

#pragma unroll
    for (int n = 0; n < TAPS; n++)
        red2[(w * TAPS + n) * 32 + lane] = acc2[n];
    __syncthreads();

    if (tid < 32) {
        float a0[TAPS], a1[TAPS];
        float m0 = 0.f, m1 = 0.f;
#pragma unroll
        for (int n = 0; n < TAPS; n++) {
            ull s2 = red2[n * 32 + tid];
#pragma unroll
            for (int gg = 1; gg < 16; gg++)
                s2 = add2(s2, red2[(gg * TAPS + n) * 32 + tid]);
            float v0, v1; unpack2(s2, v0, v1);
            float bn = __ldg(bs + n);
            a0[n] = v0 + bn; a1[n] = v1 + bn;
            m0 += a0[n];     m1 += a1[n];
        }
        m0 *= (1.f / 9.f);  m1 *= (1.f / 9.f);
        float s0 = 0.f, s1 = 0.f;
#pragma unroll
        for (int n = 0; n < TAPS; n++) {
            float d0 = a0[n] - m0, d1 = a1[n] - m1;
            s0 = fmaf(d0, d0, s0); s1 = fmaf(d1, d1, s1);
        }
        float i0 = GAIN_OVER_K / (sqrtf(s0 * (1.f / 8.f)) + 1e-10f);
        float i1 = GAIN_OVER_K / (sqrtf(s1 * (1.f / 8.f)) + 1e-10f);
        const int pix2 = bx * 64 + 2 * tid;
        float* sp = g_sf + (size_t)b * TAPS * HW + pix2;
#pragma unroll
        for (int n = 0; n < TAPS; n++)
            *(ull*)(sp + n * HW) = pack2((a0[n] - m0) * i0, (a1[n] - m1) * i1);
    }
}

// ---------------------------------------------------------------------------
// Kernel 2: MLP + per-channel normalize -> cf. Grid (16 chunks, 8 batch).
// ---------------------------------------------------------------------------
__global__ void __launch_bounds__(256) k2_mlp_cf(
    const float* __restrict__ w1, const float* __restrict__ b1,
    const float* __restrict__ w2, const float* __restrict__ b2,
    const float* __restrict__ fn_std)
{
    __shared__ float pooled_s[CC];
    __shared__ float y1_s[52];
    __shared__ float w2c[144 * MID];
    __shared__ float y2_s[144];

    const int cg   = blockIdx.x;
    const int b    = blockIdx.y;
    const int tid  = threadIdx.x;
    const int warp = tid >> 5;
    const int lane = tid & 31;

    pooled_s[tid] = g_pooled[b * CC + tid];

    {
        const float4* src = (const float4*)(w2 + (size_t)cg * 144 * MID);
#pragma unroll
        for (int i = tid; i < 144 * MID / 4; i += 256)
            ((float4*)w2c)[i] = __ldg(src + i);
    }
    __syncthreads();

    for (int j = warp; j < MID; j += 8) {
        const float* wr = w1 + j * CC;
        float s = 0.f;
#pragma unroll
        for (int k = 0; k < CC / 32; k++)
            s = fmaf(pooled_s[lane + k * 32], __ldg(wr + lane + k * 32), s);
#pragma unroll
        for (int o = 16; o > 0; o >>= 1) s += __shfl_xor_sync(0xffffffffu, s, o);
        if (lane == 0) y1_s[j] = fmaxf(s + __ldg(b1 + j), 0.f);
    }
    __syncthreads();

    if (tid < 144) {
        const int r = cg * 144 + tid;
        float a = __ldg(b2 + r);
        const float* row = w2c + tid * MID;
#pragma unroll
        for (int m = 0; m < MID; m++) a = fmaf(y1_s[m], row[m], a);
        y2_s[tid] = a;
    }
    __syncthreads();

    if (tid < 16) {
        const int c = cg * 16 + tid;
        float y[TAPS];
        float m = 0.f;
#pragma unroll
        for (int k = 0; k < TAPS; k++) { y[k] = y2_s[tid * TAPS + k]; m += y[k]; }
        m *= (1.f / 9.f);
        float ss = 0.f;
#pragma unroll
        for (int k = 0; k < TAPS; k++) { float d = y[k] - m; ss = fmaf(d, d, ss); }
        float inv = 1.f / (sqrtf(ss * (1.f / 8.f)) + 1e-10f);
#pragma unroll
        for (int k = 0; k < TAPS; k++)
            g_cf[(size_t)b * CKK + c * TAPS + k] =
                (y[k] - m) * inv * __ldg(fn_std + c * TAPS + k);
    }
}

// ---------------------------------------------------------------------------
// Kernel 3: DDF combine, f32x2, 8 channels per block (high occupancy).
// Block (28,8)=224 thr; thread = 1 row x 2 cols. Grid (7, 32, 8).
// ---------------------------------------------------------------------------
#define K3_CG 8
#define HSTR 60
#define HSZ  (10 * HSTR)
__global__ void __launch_bounds__(224) k3_ddf(
    const float* __restrict__ x, float* __restrict__ out)
{
    __shared__ __align__(16) float xh[K3_CG * HSZ];     // 19.2 KB
    __shared__ __align__(16) ull cf2_s[K3_CG * TAPS];   // 576 B

    const int b  = blockIdx.z;
    const int cg = blockIdx.y;
    const int r0 = blockIdx.x * 8;
    const int tx = threadIdx.x;
    const int ty = threadIdx.y;
    const int tid = ty * 28 + tx;

    const int row = r0 + ty;
    const int col = 2 * tx;

    if (tid < K3_CG * TAPS) {
        float v = g_cf[(size_t)b * CKK + cg * K3_CG * TAPS + tid];
        cf2_s[tid] = pack2(v, v);
    }

    ull sfr[TAPS];
    {
        const float* sp = g_sf + (size_t)b * TAPS * HW + row * WW + col;
#pragma unroll
        for (int n = 0; n < TAPS; n++)
            sfr[n] = __ldg((const ull*)(sp + n * HW));
    }

    int  idx[3]; const float* ptr[3]; bool vld[3], has[3];
#pragma unroll
    for (int s = 0; s < 3; s++) {
        int i = tid + s * 224;
        has[s] = (i < 580);
        int ii = has[s] ? i : 0;
        int rr = ii / 58, jj = ii % 58;
        int gr = r0 - 1 + rr, gc = jj - 1;
        vld[s] = has[s] && (gr >= 0) && (gr < HH) && (gc >= 0) && (gc < WW);
        idx[s] = rr * HSTR + jj;
        ptr[s] = x + ((size_t)b * CC + cg * K3_CG) * HW + gr * WW + gc;
    }

#pragma unroll
    for (int g = 0; g < K3_CG; g++) {
#pragma unroll
        for (int s = 0; s < 3; s++) {
            float v = vld[s] ? __ldg(ptr[s] + (size_t)g * HW) : 0.f;
            if (has[s]) xh[g * HSZ + idx[s]] = v;
        }
    }
    __syncthreads();

    const float* hbase = xh + ty * HSTR + col;
    float* po = out + ((size_t)b * CC + cg * K3_CG) * HW + row * WW + col;

#pragma unroll
    for (int g = 0; g < K3_CG; g++) {
        const float* hp = hbase + g * HSZ;
        ull acc = 0ULL;
        const ull* cfp = cf2_s + g * TAPS;

#pragma unroll
        for (int u = 0; u < KK; u++) {
            ull A = *(const ull*)(hp + u * HSTR);
            ull B = *(const ull*)(hp + u * HSTR + 2);
            float alo, ahi, blo, bhi;
            unpack2(A, alo, ahi);
            unpack2(B, blo, bhi);
            ull M = pack2(ahi, blo);
            acc = fma2(A, mul2(cfp[u * 3 + 0], sfr[u * 3 + 0]), acc);
            acc = fma2(M, mul2(cfp[u * 3 + 1], sfr[u * 3 + 1]), acc);
            acc = fma2(B, mul2(cfp[u * 3 + 2], sfr[u * 3 + 2]), acc);
        }

        *(ull*)po = acc;
        po += HW;
    }
}

// ---------------------------------------------------------------------------
extern "C" void kernel_launch(void* const* d_in, const int* in_sizes, int n_in,
                              void* d_out, int out_size)
{
    const float* x      = (const float*)d_in[0];
    const float* w1     = (const float*)d_in[1];
    const float* b1     = (const float*)d_in[2];
    const float* w2     = (const float*)d_in[3];
    const float* b2     = (const float*)d_in[4];
    const float* ws     = (const float*)d_in[5];
    const float* bs     = (const float*)d_in[6];
    const float* fn_std = (const float*)d_in[7];
    float* out = (float*)d_out;

    dim3 gA(49 + 16, BB);            // 49 sf tiles (64 px) + 16 pooling blocks
    kA_sf_pool<<<gA, 512>>>(x, ws, bs);

    dim3 g2(16, BB);
    k2_mlp_cf<<<g2, 256>>>(w1, b1, w2, b2, fn_std);

    dim3 g3(HH / 8, CC / K3_CG, BB);
    dim3 b3(28, 8);
    k3_ddf<<<g3, b3>>>(x, out);
}